// round 15
// baseline (speedup 1.0000x reference)
#include <cuda_runtime.h>
#include <cuda_fp16.h>
#include <cstdint>

#define NB 16
#define NTH 512          // 16 warps: 0-6 layer0, 7-15 layer1
#define HH 50
#define TSTEPS 512
#define IIN 12
#define BTOT 2048

#define KP0H 72          // I0 row stride in halves: K=64 + 8 pad (144B ≡ 16 mod 128)
#define KP1H 120         // I1 row stride in halves: K=112 + 8 pad (240B ≡ 112 mod 128)
#define H1OFF 56         // h1 offset (halves) inside l1 concat input [h0(50)|pad6|h1(50)|pad6]

static __device__ __forceinline__ uint32_t smem_u32(const void* p) {
    uint32_t a;
    asm("{ .reg .u64 t; cvta.to.shared.u64 t, %1; cvt.u32.u64 %0, t; }" : "=r"(a) : "l"(p));
    return a;
}
static __device__ __forceinline__ uint32_t h2pack(float a, float b) {
    __half2 h = __halves2half2(__float2half_rn(a), __float2half_rn(b));
    return *reinterpret_cast<uint32_t*>(&h);
}
static __device__ __forceinline__ void ldmx4(uint32_t* a, uint32_t addr) {
    asm volatile("ldmatrix.sync.aligned.m8n8.x4.shared.b16 {%0,%1,%2,%3}, [%4];"
        : "=r"(a[0]), "=r"(a[1]), "=r"(a[2]), "=r"(a[3]) : "r"(addr));
}
static __device__ __forceinline__ void mma16(float* c, const uint32_t* a, uint32_t b0, uint32_t b1) {
    asm volatile("mma.sync.aligned.m16n8k16.row.col.f32.f16.f16.f32 "
        "{%0,%1,%2,%3}, {%4,%5,%6,%7}, {%8,%9}, {%0,%1,%2,%3};"
        : "+f"(c[0]), "+f"(c[1]), "+f"(c[2]), "+f"(c[3])
        : "r"(a[0]), "r"(a[1]), "r"(a[2]), "r"(a[3]), "r"(b0), "r"(b1));
}
__device__ __forceinline__ float tanha(float x) {
    float r; asm("tanh.approx.f32 %0, %1;" : "=f"(r) : "f"(x)); return r;
}
// packed f16x2 tanh (MUFU, 2 values per inst)
static __device__ __forceinline__ uint32_t tanh2u(uint32_t v) {
    uint32_t r; asm("tanh.approx.f16x2 %0, %1;" : "=r"(r) : "r"(v)); return r;
}
static __device__ __forceinline__ uint32_t f2h2(float a, float b) {
    __half2 h = __floats2half2_rn(a, b);
    return *reinterpret_cast<uint32_t*>(&h);
}
static __device__ __forceinline__ float2 h22f2(uint32_t v) {
    __half2 h = *reinterpret_cast<__half2*>(&v);
    return __half22float2(h);
}
// permuted gate rows: row' = 4*j + gate  <->  original row = j + 50*gate
static __device__ __forceinline__ int orow(int rp) { return (rp >> 2) + 50 * (rp & 3); }
// layer0 concat k (64): [x(12)|h0(50)|pad2]
__device__ __forceinline__ float wl0(const float* wi, const float* wh, int r, int f) {
    if (f < IIN) return wi[r * IIN + f];
    if (f < IIN + HH) return wh[r * HH + (f - IIN)];
    return 0.f;
}
// layer1 concat k (112): [h0(50)|pad6|h1(50)|pad6]
__device__ __forceinline__ float wl1(const float* wi, const float* wh, int r, int f) {
    if (f < HH) return wi[r * HH + f];
    if (f >= H1OFF && f < H1OFF + HH) return wh[r * HH + (f - H1OFF)];
    return 0.f;
}

__global__ void __launch_bounds__(NTH, 1)
lstm_kernel(const float* __restrict__ x,
            const float* __restrict__ w_ih0, const float* __restrict__ w_hh0,
            const float* __restrict__ b_ih0, const float* __restrict__ b_hh0,
            const float* __restrict__ w_ih1, const float* __restrict__ w_hh1,
            const float* __restrict__ b_ih1, const float* __restrict__ b_hh1,
            const float* __restrict__ w_out, const float* __restrict__ b_out,
            float* __restrict__ out) {
    __shared__ __half I0[2 * 16 * KP0H];
    __shared__ __half I1[2 * 16 * KP1H];

    const int tid  = threadIdx.x;
    const int lane = tid & 31;
    const int w    = tid >> 5;
    const int bbase = blockIdx.x * NB;

    for (int i = tid; i < 2 * 16 * KP0H; i += NTH) I0[i] = __float2half(0.f);
    for (int i = tid; i < 2 * 16 * KP1H; i += NTH) I1[i] = __float2half(0.f);
    __syncthreads();
    if (tid < 96) {   // stage x(0)
        int b = tid / 6, p = tid % 6;
        float2 v = *reinterpret_cast<const float2*>(&x[(size_t)(bbase + b) * TSTEPS * IIN + 2 * p]);
        *reinterpret_cast<__half2*>(&I0[b * KP0H + 2 * p]) =
            __halves2half2(__float2half_rn(v.x), __float2half_rn(v.y));
    }
    __syncthreads();

    // ldmatrix per-lane source address components
    const int lrow = (lane & 7) + 8 * ((lane >> 3) & 1);
    const int lkq  = (lane >> 4) & 1;
    const int m    = lane & 3;
    const int bofs = (lane >> 2) + 8 * (m & 1);   // batch this lane finalizes

    if (w < 7) {
        // ================= LAYER-0 GROUP: warp w owns ntiles 4w..4w+3 =================
        uint32_t wb[4][4][2];
        float bf[4][2];
#pragma unroll
        for (int u = 0; u < 4; u++) {
            int t = 4 * w + u;
            int nr = t * 8 + (lane >> 2);
            bool ok = nr < 200;
            int org = ok ? orow(nr) : 0;
#pragma unroll
            for (int kt = 0; kt < 4; kt++) {
                int k0 = kt * 16 + 2 * m;
                wb[u][kt][0] = ok ? h2pack(wl0(w_ih0, w_hh0, org, k0),
                                           wl0(w_ih0, w_hh0, org, k0 + 1)) : 0u;
                wb[u][kt][1] = ok ? h2pack(wl0(w_ih0, w_hh0, org, k0 + 8),
                                           wl0(w_ih0, w_hh0, org, k0 + 9)) : 0u;
            }
            int c0 = t * 8 + 2 * m;
            bf[u][0] = (c0 < 200)     ? (b_ih0[orow(c0)]     + b_hh0[orow(c0)])     : 0.f;
            bf[u][1] = (c0 + 1 < 200) ? (b_ih0[orow(c0 + 1)] + b_hh0[orow(c0 + 1)]) : 0.f;
        }
        const uint32_t abase = smem_u32(I0) + (uint32_t)(lrow * KP0H) * 2u + (uint32_t)lkq * 16u;
        float cst[4] = {0.f, 0.f, 0.f, 0.f};
        const int xb = tid / 6, xp = tid % 6;

        for (int s = 0; s <= TSTEPS; s++) {
            if (s < TSTEPS) {
                float2 xpv;
                const bool dox = (tid < 96) && (s + 1 < TSTEPS);
                if (dox)
                    xpv = *reinterpret_cast<const float2*>(
                        &x[((size_t)(bbase + xb) * TSTEPS + (s + 1)) * IIN + 2 * xp]);

                float acc[4][4];
#pragma unroll
                for (int u = 0; u < 4; u++) {
                    acc[u][0] = bf[u][0]; acc[u][1] = bf[u][1];
                    acc[u][2] = bf[u][0]; acc[u][3] = bf[u][1];
                }
                uint32_t ab = abase + (uint32_t)(s & 1) * (16 * KP0H * 2);
#pragma unroll
                for (int kt = 0; kt < 4; kt++) {
                    uint32_t a[4];
                    ldmx4(a, ab + kt * 32);
#pragma unroll
                    for (int u = 0; u < 4; u++)
                        mma16(acc[u], a, wb[u][kt][0], wb[u][kt][1]);
                }
                // fused update, activation pairs in f16x2 MUFU
                __half* I0n = I0 + ((s + 1) & 1) * 16 * KP0H;
                __half* I1c = I1 + (s & 1) * 16 * KP1H;
#pragma unroll
                for (int p = 0; p < 2; p++) {
                    float gv[2][4];
#pragma unroll
                    for (int q = 0; q < 2; q++) {
                        int u = 2 * p + q;
                        float t0 = __shfl_xor_sync(0xffffffffu, (m & 1) ? acc[u][0] : acc[u][2], 1);
                        float t1 = __shfl_xor_sync(0xffffffffu, (m & 1) ? acc[u][1] : acc[u][3], 1);
                        if (!(m & 1)) { gv[q][0] = acc[u][0]; gv[q][1] = acc[u][1]; gv[q][2] = t0; gv[q][3] = t1; }
                        else          { gv[q][0] = t0;        gv[q][1] = t1;        gv[q][2] = acc[u][2]; gv[q][3] = acc[u][3]; }
                    }
                    float2 si = h22f2(tanh2u(f2h2(0.5f * gv[0][0], 0.5f * gv[1][0])));
                    float2 sf = h22f2(tanh2u(f2h2(0.5f * gv[0][1], 0.5f * gv[1][1])));
                    float2 tg = h22f2(tanh2u(f2h2(gv[0][2], gv[1][2])));
                    float2 so = h22f2(tanh2u(f2h2(0.5f * gv[0][3], 0.5f * gv[1][3])));
                    float i0 = fmaf(0.5f, si.x, 0.5f), i1 = fmaf(0.5f, si.y, 0.5f);
                    float f0 = fmaf(0.5f, sf.x, 0.5f), f1 = fmaf(0.5f, sf.y, 0.5f);
                    float o0 = fmaf(0.5f, so.x, 0.5f), o1 = fmaf(0.5f, so.y, 0.5f);
                    float cc0 = f0 * cst[2 * p]     + i0 * tg.x;
                    float cc1 = f1 * cst[2 * p + 1] + i1 * tg.y;
                    cst[2 * p] = cc0; cst[2 * p + 1] = cc1;
                    float2 tc = h22f2(tanh2u(f2h2(cc0, cc1)));
                    int j0 = 2 * (4 * w + 2 * p) + (m >> 1);
                    int j1 = j0 + 2;
                    if (j0 < HH) {
                        __half hv = __float2half_rn(o0 * tc.x);
                        I0n[bofs * KP0H + IIN + j0] = hv;
                        I1c[bofs * KP1H + j0]       = hv;
                    }
                    if (j1 < HH) {
                        __half hv = __float2half_rn(o1 * tc.y);
                        I0n[bofs * KP0H + IIN + j1] = hv;
                        I1c[bofs * KP1H + j1]       = hv;
                    }
                }
                if (dox)
                    *reinterpret_cast<__half2*>(&I0n[xb * KP0H + 2 * xp]) =
                        __halves2half2(__float2half_rn(xpv.x), __float2half_rn(xpv.y));
            }
            __syncthreads();
        }
    } else {
        // ================= LAYER-1 GROUP: warp (w-7) owns ntiles 3i..3i+2 =================
        const int i1 = w - 7;
        uint32_t wb[3][7][2];
        float bf[3][2];
#pragma unroll
        for (int u = 0; u < 3; u++) {
            int t = 3 * i1 + u;
            int nr = t * 8 + (lane >> 2);
            bool ok = nr < 200;
            int org = ok ? orow(nr) : 0;
#pragma unroll
            for (int kt = 0; kt < 7; kt++) {
                int k0 = kt * 16 + 2 * m;
                wb[u][kt][0] = ok ? h2pack(wl1(w_ih1, w_hh1, org, k0),
                                           wl1(w_ih1, w_hh1, org, k0 + 1)) : 0u;
                wb[u][kt][1] = ok ? h2pack(wl1(w_ih1, w_hh1, org, k0 + 8),
                                           wl1(w_ih1, w_hh1, org, k0 + 9)) : 0u;
            }
            int c0 = t * 8 + 2 * m;
            bf[u][0] = (c0 < 200)     ? (b_ih1[orow(c0)]     + b_hh1[orow(c0)])     : 0.f;
            bf[u][1] = (c0 + 1 < 200) ? (b_ih1[orow(c0 + 1)] + b_hh1[orow(c0 + 1)]) : 0.f;
        }
        const uint32_t abase = smem_u32(I1) + (uint32_t)(lrow * KP1H) * 2u + (uint32_t)lkq * 16u;
        float cst[3] = {0.f, 0.f, 0.f};

        for (int s = 0; s <= TSTEPS; s++) {
            if (s >= 1) {
                float acc[3][4];
#pragma unroll
                for (int u = 0; u < 3; u++) {
                    acc[u][0] = bf[u][0]; acc[u][1] = bf[u][1];
                    acc[u][2] = bf[u][0]; acc[u][3] = bf[u][1];
                }
                uint32_t ab = abase + (uint32_t)((s - 1) & 1) * (16 * KP1H * 2);
#pragma unroll
                for (int kt = 0; kt < 7; kt++) {
                    uint32_t a[4];
                    ldmx4(a, ab + kt * 32);
#pragma unroll
                    for (int u = 0; u < 3; u++)
                        mma16(acc[u], a, wb[u][kt][0], wb[u][kt][1]);
                }
                __half* I1c = I1 + (s & 1) * 16 * KP1H;

                // gather gates for all 3 u
                float gv[3][4];
#pragma unroll
                for (int u = 0; u < 3; u++) {
                    float t0 = __shfl_xor_sync(0xffffffffu, (m & 1) ? acc[u][0] : acc[u][2], 1);
                    float t1 = __shfl_xor_sync(0xffffffffu, (m & 1) ? acc[u][1] : acc[u][3], 1);
                    if (!(m & 1)) { gv[u][0] = acc[u][0]; gv[u][1] = acc[u][1]; gv[u][2] = t0; gv[u][3] = t1; }
                    else          { gv[u][0] = t0;        gv[u][1] = t1;        gv[u][2] = acc[u][2]; gv[u][3] = acc[u][3]; }
                }
                // pair u=0,1
                {
                    float2 si = h22f2(tanh2u(f2h2(0.5f * gv[0][0], 0.5f * gv[1][0])));
                    float2 sf = h22f2(tanh2u(f2h2(0.5f * gv[0][1], 0.5f * gv[1][1])));
                    float2 tg = h22f2(tanh2u(f2h2(gv[0][2], gv[1][2])));
                    float2 so = h22f2(tanh2u(f2h2(0.5f * gv[0][3], 0.5f * gv[1][3])));
                    float i0 = fmaf(0.5f, si.x, 0.5f), i1v = fmaf(0.5f, si.y, 0.5f);
                    float f0 = fmaf(0.5f, sf.x, 0.5f), f1 = fmaf(0.5f, sf.y, 0.5f);
                    float o0 = fmaf(0.5f, so.x, 0.5f), o1 = fmaf(0.5f, so.y, 0.5f);
                    float cc0 = f0 * cst[0] + i0 * tg.x;
                    float cc1 = f1 * cst[1] + i1v * tg.y;
                    cst[0] = cc0; cst[1] = cc1;
                    float2 tc = h22f2(tanh2u(f2h2(cc0, cc1)));
                    int j0 = 2 * (3 * i1) + (m >> 1);
                    int j1 = j0 + 2;
                    if (j0 < HH) I1c[bofs * KP1H + H1OFF + j0] = __float2half_rn(o0 * tc.x);
                    if (j1 < HH) I1c[bofs * KP1H + H1OFF + j1] = __float2half_rn(o1 * tc.y);
                }
                // single u=2: pair (gi,gf) and (gg, 0.5*go)
                {
                    float2 sa = h22f2(tanh2u(f2h2(0.5f * gv[2][0], 0.5f * gv[2][1])));
                    float2 sb = h22f2(tanh2u(f2h2(gv[2][2], 0.5f * gv[2][3])));
                    float i_ = fmaf(0.5f, sa.x, 0.5f), f_ = fmaf(0.5f, sa.y, 0.5f);
                    float g_ = sb.x, o_ = fmaf(0.5f, sb.y, 0.5f);
                    float cc = f_ * cst[2] + i_ * g_;
                    cst[2] = cc;
                    int j = 2 * (3 * i1 + 2) + (m >> 1);
                    if (j < HH) I1c[bofs * KP1H + H1OFF + j] = __float2half_rn(o_ * tanha(cc));
                }
            }
            __syncthreads();
        }
    }

    // head: h1(511) is in I1 buffer (512&1)=0
    if (tid < NB) {
        float acc = b_out[0];
        const __half* hb = I1 + tid * KP1H + H1OFF;
#pragma unroll
        for (int j = 0; j < HH; j++) acc += w_out[j] * __half2float(hb[j]);
        float e = __expf(-acc);
        out[bbase + tid] = __fdividef(1.0f, 1.0f + e);
    }
}

extern "C" void kernel_launch(void* const* d_in, const int* in_sizes, int n_in,
                              void* d_out, int out_size) {
    const float* x     = (const float*)d_in[0];
    const float* w_ih0 = (const float*)d_in[1];
    const float* w_hh0 = (const float*)d_in[2];
    const float* b_ih0 = (const float*)d_in[3];
    const float* b_hh0 = (const float*)d_in[4];
    const float* w_ih1 = (const float*)d_in[5];
    const float* w_hh1 = (const float*)d_in[6];
    const float* b_ih1 = (const float*)d_in[7];
    const float* b_hh1 = (const float*)d_in[8];
    const float* w_out = (const float*)d_in[9];
    const float* b_out = (const float*)d_in[10];
    float* out = (float*)d_out;

    lstm_kernel<<<BTOT / NB, NTH>>>(
        x, w_ih0, w_hh0, b_ih0, b_hh0, w_ih1, w_hh1, b_ih1, b_hh1, w_out, b_out, out);
}